// round 8
// baseline (speedup 1.0000x reference)
#include <cuda_runtime.h>

#define NN 64
#define CC 64
#define HH 128
#define WW 128
#define HWSZ (HH * WW)
#define OH 126
#define OW 126
#define OUT_ROWS_PER_TILE 16
#define N_TILES 8
#define TILE_ROWS 18          // 16 output rows + 2 halo
#define TILE_STRIDE 132       // padded row, keeps 16B alignment
#define SM_TILE (TILE_ROWS * TILE_STRIDE)
#define STAGES 3
#define NTHREADS 128
#define CP_PER_STAGE (TILE_ROWS * 32)   // 576 float4 copies
#define WSTRIDE 20            // 9 weights duplicated (18 floats) + pad, 8B-aligned

typedef unsigned long long u64;

__device__ __forceinline__ void cp_async16(const float* smem, const float* gmem) {
    unsigned saddr = (unsigned)__cvta_generic_to_shared((void*)smem);
    asm volatile("cp.async.cg.shared.global [%0], [%1], 16;\n" :: "r"(saddr), "l"(gmem));
}
__device__ __forceinline__ void cp_commit() {
    asm volatile("cp.async.commit_group;\n" ::: "memory");
}
__device__ __forceinline__ void cp_wait1() {
    asm volatile("cp.async.wait_group 1;\n" ::: "memory");
}
__device__ __forceinline__ void cp_wait0() {
    asm volatile("cp.async.wait_group 0;\n" ::: "memory");
}

// Packed fp32x2 FMA: d.lo += a.lo*w.lo; d.hi += a.hi*w.hi  (one issue slot)
__device__ __forceinline__ void ffma2(u64& d, u64 a, u64 w) {
    asm("fma.rn.f32x2 %0, %1, %2, %0;" : "+l"(d) : "l"(a), "l"(w));
}
__device__ __forceinline__ u64 pack2(float lo, float hi) {
    u64 r; asm("mov.b64 %0, {%1, %2};" : "=l"(r) : "f"(lo), "f"(hi)); return r;
}
__device__ __forceinline__ void unpack2(u64 v, float& lo, float& hi) {
    asm("mov.b64 {%0, %1}, %2;" : "=f"(lo), "=f"(hi) : "l"(v));
}

// One channel of 3x3 conv on a 4-row x 4-col patch, f32x2-packed.
// acc[8]: for ro=0..3, acc[2*ro]=cols(0,1), acc[2*ro+1]=cols(2,3).
__device__ __forceinline__ void compute_ch(const float* __restrict__ t,
                                           const float* __restrict__ wch,  // duplicated weights
                                           u64* __restrict__ acc) {
    u64 w[9];
    #pragma unroll
    for (int i = 0; i < 9; ++i) w[i] = *(const u64*)(wch + 2 * i);   // LDS.64 broadcast (w,w)

    #pragma unroll
    for (int j = 0; j < 6; ++j) {                 // 6 input rows -> 4 output rows
        const u64* r64 = (const u64*)(t + j * TILE_STRIDE);          // 16B-aligned
        const u64 A = r64[0];    // (v0,v1)
        const u64 C = r64[1];    // (v2,v3)
        const u64 E = r64[2];    // (v4,v5)
        float a0, a1, c0, c1, e0, e1;
        unpack2(A, a0, a1); unpack2(C, c0, c1); unpack2(E, e0, e1);
        const u64 B = pack2(a1, c0);   // (v1,v2)
        const u64 D = pack2(c1, e0);   // (v3,v4)
        #pragma unroll
        for (int kh = 0; kh < 3; ++kh) {
            const int ro = j - kh;                // compile-time after unroll
            if (ro >= 0 && ro < 4) {
                const u64 w0 = w[kh * 3 + 0], w1 = w[kh * 3 + 1], w2 = w[kh * 3 + 2];
                ffma2(acc[2 * ro + 0], A, w0);
                ffma2(acc[2 * ro + 0], B, w1);
                ffma2(acc[2 * ro + 0], C, w2);
                ffma2(acc[2 * ro + 1], C, w0);
                ffma2(acc[2 * ro + 1], D, w1);
                ffma2(acc[2 * ro + 1], E, w2);
            }
        }
    }
}

__global__ __launch_bounds__(NTHREADS, 7)
void imagewise_conv2d_kernel(const float* __restrict__ img,
                             const float* __restrict__ ker,
                             float* __restrict__ out) {
    __shared__ __align__(8)  float wts[CC * WSTRIDE];      // duplicated weights
    __shared__ __align__(16) float tile[STAGES][SM_TILE];  // 3-stage ring

    const int n     = blockIdx.x;
    const int yt    = blockIdx.y;
    const int tid   = threadIdx.x;
    const int tx    = tid & 31;        // 32 col-groups x 4 cols
    const int ty    = tid >> 5;        // 4 row-groups  x 4 rows
    const int x0    = tx * 4;
    const int y0    = ty * 4;
    const int ybase = yt * OUT_ROWS_PER_TILE;

    // ---- stage weights, each value duplicated for f32x2 broadcast ----
    {
        const float* kn = ker + (size_t)n * CC * 9;
        for (int e = tid; e < CC * 9; e += NTHREADS) {
            int c = e / 9;
            int i = e - c * 9;
            float v = kn[e];
            wts[c * WSTRIDE + 2 * i]     = v;
            wts[c * WSTRIDE + 2 * i + 1] = v;
        }
    }

    // ---- hoisted copy descriptors (loop-invariant across channels) ----
    int soff[5], goff[5];
    #pragma unroll
    for (int k = 0; k < 5; ++k) {
        int idx = tid + k * NTHREADS;
        if (idx < CP_PER_STAGE) {
            int r  = idx >> 5;
            int c4 = (idx & 31) * 4;
            int rg = ybase + r; if (rg > HH - 1) rg = HH - 1;   // clamp halo
            soff[k] = r * TILE_STRIDE + c4;
            goff[k] = rg * WW + c4;
        } else {
            soff[k] = 0; goff[k] = 0;
        }
    }
    const int  s0 = soff[0], s1 = soff[1], s2 = soff[2], s3 = soff[3], s4 = soff[4];
    const int  g0 = goff[0], g1 = goff[1], g2 = goff[2], g3 = goff[3], g4 = goff[4];
    const bool has5 = (tid + 4 * NTHREADS) < CP_PER_STAGE;   // tid < 64

    const float* imgn = img + (size_t)n * CC * HWSZ;

    auto issue = [&](float* sbase, const float* g) {
        cp_async16(sbase + s0, g + g0);
        cp_async16(sbase + s1, g + g1);
        cp_async16(sbase + s2, g + g2);
        cp_async16(sbase + s3, g + g3);
        if (has5) cp_async16(sbase + s4, g + g4);
        cp_commit();
    };

    // ---- prologue: channels 0 and 1 into stages 0 and 1 ----
    const float* src = imgn;
    issue(&tile[0][0], src); src += HWSZ;
    issue(&tile[1][0], src); src += HWSZ;      // src now -> channel 2

    u64 acc[8];
    #pragma unroll
    for (int i = 0; i < 8; ++i) acc[i] = 0ull;

    const int yx = y0 * TILE_STRIDE + x0;
    const float* wp = wts;
    int cur = 0, nxt = 2;                      // nxt = (cur + 2) % 3

    for (int c = 0; c < CC; ++c) {
        if (c + 1 < CC) cp_wait1(); else cp_wait0();
        __syncthreads();   // c's data visible; compute of c-1 (stage nxt) done

        if (c + 2 < CC) { issue(&tile[nxt][0], src); src += HWSZ; }

        compute_ch(&tile[cur][yx], wp, acc);
        wp += WSTRIDE;
        cur = (cur == STAGES - 1) ? 0 : cur + 1;
        nxt = (nxt == STAGES - 1) ? 0 : nxt + 1;
    }

    // ---- store (mask 126-row/col edges) ----
    const int gy0 = ybase + y0;
    #pragma unroll
    for (int ry = 0; ry < 4; ++ry) {
        const int y = gy0 + ry;
        if (y < OH) {
            float* o = out + ((size_t)n * OH + y) * OW + x0;
            float r0, r1, r2, r3;
            unpack2(acc[2 * ry + 0], r0, r1);
            unpack2(acc[2 * ry + 1], r2, r3);
            if (x0 + 0 < OW) o[0] = r0;
            if (x0 + 1 < OW) o[1] = r1;
            if (x0 + 2 < OW) o[2] = r2;
            if (x0 + 3 < OW) o[3] = r3;
        }
    }
}

extern "C" void kernel_launch(void* const* d_in, const int* in_sizes, int n_in,
                              void* d_out, int out_size) {
    const float* img = (const float*)d_in[0];   // [64,64,128,128] f32
    const float* ker = (const float*)d_in[1];   // [64,64,3,3]     f32
    float* out       = (float*)d_out;           // [64,1,126,126]  f32

    dim3 grid(NN, N_TILES);
    imagewise_conv2d_kernel<<<grid, NTHREADS>>>(img, ker, out);
}

// round 9
// speedup vs baseline: 1.0360x; 1.0360x over previous
#include <cuda_runtime.h>

#define NN 64
#define CC 64
#define NSPLIT 2
#define CH_PER (CC / NSPLIT)   // 32 channels per CTA
#define HH 128
#define WW 128
#define HWSZ (HH * WW)
#define OH 126
#define OW 126
#define OUT_ROWS_PER_TILE 16
#define N_TILES 8
#define TILE_ROWS 18          // 16 output rows + 2 halo
#define TILE_STRIDE 132       // padded row, keeps 16B alignment
#define SM_TILE (TILE_ROWS * TILE_STRIDE)
#define STAGES 3
#define NTHREADS 128
#define CP_PER_STAGE (TILE_ROWS * 32)   // 576 float4 copies
#define OUT_ELEMS (NN * OH * OW)        // 1016064 floats (divisible by 4)

__device__ __forceinline__ void cp_async16(const float* smem, const float* gmem) {
    unsigned saddr = (unsigned)__cvta_generic_to_shared((void*)smem);
    asm volatile("cp.async.cg.shared.global [%0], [%1], 16;\n" :: "r"(saddr), "l"(gmem));
}
__device__ __forceinline__ void cp_commit() {
    asm volatile("cp.async.commit_group;\n" ::: "memory");
}
__device__ __forceinline__ void cp_wait1() {
    asm volatile("cp.async.wait_group 1;\n" ::: "memory");
}
__device__ __forceinline__ void cp_wait0() {
    asm volatile("cp.async.wait_group 0;\n" ::: "memory");
}

// One channel of 3x3 conv on a 4-row x 4-col output patch. Weights packed 3xfloat4.
__device__ __forceinline__ void compute_ch(const float* __restrict__ t,
                                           const float4* __restrict__ w4,
                                           float* __restrict__ acc) {
    const float4 wa = w4[0];
    const float4 wb = w4[1];
    const float w8  = ((const float*)(w4 + 2))[0];
    const float w0 = wa.x, w1 = wa.y, w2 = wa.z, w3 = wa.w;
    const float w4_ = wb.x, w5 = wb.y, w6 = wb.z, w7 = wb.w;

    #pragma unroll
    for (int j = 0; j < 6; ++j) {                 // 6 input rows -> 4 output rows
        const float* row = t + j * TILE_STRIDE;
        const float4 p = *(const float4*)(row);
        const float2 q = *(const float2*)(row + 4);
        const float v0 = p.x, v1 = p.y, v2 = p.z, v3 = p.w, v4 = q.x, v5 = q.y;
        #pragma unroll
        for (int kh = 0; kh < 3; ++kh) {
            const int ro = j - kh;                // compile-time after unroll
            if (ro >= 0 && ro < 4) {
                const float a  = (kh == 0) ? w0 : (kh == 1) ? w3 : w6;
                const float b  = (kh == 0) ? w1 : (kh == 1) ? w4_ : w7;
                const float cc = (kh == 0) ? w2 : (kh == 1) ? w5 : w8;
                acc[ro * 4 + 0] = fmaf(v0, a,  acc[ro * 4 + 0]);
                acc[ro * 4 + 0] = fmaf(v1, b,  acc[ro * 4 + 0]);
                acc[ro * 4 + 0] = fmaf(v2, cc, acc[ro * 4 + 0]);
                acc[ro * 4 + 1] = fmaf(v1, a,  acc[ro * 4 + 1]);
                acc[ro * 4 + 1] = fmaf(v2, b,  acc[ro * 4 + 1]);
                acc[ro * 4 + 1] = fmaf(v3, cc, acc[ro * 4 + 1]);
                acc[ro * 4 + 2] = fmaf(v2, a,  acc[ro * 4 + 2]);
                acc[ro * 4 + 2] = fmaf(v3, b,  acc[ro * 4 + 2]);
                acc[ro * 4 + 2] = fmaf(v4, cc, acc[ro * 4 + 2]);
                acc[ro * 4 + 3] = fmaf(v3, a,  acc[ro * 4 + 3]);
                acc[ro * 4 + 3] = fmaf(v4, b,  acc[ro * 4 + 3]);
                acc[ro * 4 + 3] = fmaf(v5, cc, acc[ro * 4 + 3]);
            }
        }
    }
}

__global__ void zero_out_kernel(float4* __restrict__ out) {
    int i = blockIdx.x * blockDim.x + threadIdx.x;
    if (i < OUT_ELEMS / 4) out[i] = make_float4(0.f, 0.f, 0.f, 0.f);
}

__global__ __launch_bounds__(NTHREADS, 7)
void imagewise_conv2d_kernel(const float* __restrict__ img,
                             const float* __restrict__ ker,
                             float* __restrict__ out) {
    __shared__ float4 wts4[CH_PER * 3];                    // 12 floats / channel (padded)
    __shared__ __align__(16) float tile[STAGES][SM_TILE];  // 3-stage ring

    const int n     = blockIdx.x;
    const int yt    = blockIdx.y;
    const int ch0   = blockIdx.z * CH_PER;   // channel half
    const int tid   = threadIdx.x;
    const int tx    = tid & 31;        // 32 col-groups x 4 cols
    const int ty    = tid >> 5;        // 4 row-groups  x 4 rows
    const int x0    = tx * 4;
    const int y0    = ty * 4;
    const int ybase = yt * OUT_ROWS_PER_TILE;

    // ---- stage this half's weights, padded so each channel is 3 float4s ----
    {
        const float* kn = ker + (size_t)n * CC * 9 + (size_t)ch0 * 9;
        for (int e = tid; e < CH_PER * 9; e += NTHREADS) {
            int c = e / 9;
            int i = e - c * 9;
            ((float*)&wts4[c * 3])[i] = kn[e];
        }
    }

    // ---- hoisted copy descriptors (loop-invariant across channels) ----
    int soff[5], goff[5];
    #pragma unroll
    for (int k = 0; k < 5; ++k) {
        int idx = tid + k * NTHREADS;
        if (idx < CP_PER_STAGE) {
            int r  = idx >> 5;
            int c4 = (idx & 31) * 4;
            int rg = ybase + r; if (rg > HH - 1) rg = HH - 1;   // clamp halo
            soff[k] = r * TILE_STRIDE + c4;
            goff[k] = rg * WW + c4;
        } else {
            soff[k] = 0; goff[k] = 0;
        }
    }
    const int  s0 = soff[0], s1 = soff[1], s2 = soff[2], s3 = soff[3], s4 = soff[4];
    const int  g0 = goff[0], g1 = goff[1], g2 = goff[2], g3 = goff[3], g4 = goff[4];
    const bool has5 = (tid + 4 * NTHREADS) < CP_PER_STAGE;   // tid < 64

    const float* imgn = img + (size_t)n * CC * HWSZ + (size_t)ch0 * HWSZ;

    auto issue = [&](float* sbase, const float* g) {
        cp_async16(sbase + s0, g + g0);
        cp_async16(sbase + s1, g + g1);
        cp_async16(sbase + s2, g + g2);
        cp_async16(sbase + s3, g + g3);
        if (has5) cp_async16(sbase + s4, g + g4);
        cp_commit();
    };

    // ---- prologue: first two channels into stages 0 and 1 ----
    const float* src = imgn;
    issue(&tile[0][0], src); src += HWSZ;
    issue(&tile[1][0], src); src += HWSZ;      // src now -> 3rd channel of this half

    float acc[16];
    #pragma unroll
    for (int i = 0; i < 16; ++i) acc[i] = 0.0f;

    const int yx = y0 * TILE_STRIDE + x0;
    const float4* wp = wts4;
    int cur = 0, nxt = 2;                      // nxt = (cur + 2) % 3

    for (int c = 0; c < CH_PER; ++c) {
        if (c + 1 < CH_PER) cp_wait1(); else cp_wait0();
        __syncthreads();   // c's data visible; compute of c-1 (stage nxt) done

        if (c + 2 < CH_PER) { issue(&tile[nxt][0], src); src += HWSZ; }

        compute_ch(&tile[cur][yx], wp, acc);
        wp += 3;
        cur = (cur == STAGES - 1) ? 0 : cur + 1;
        nxt = (nxt == STAGES - 1) ? 0 : nxt + 1;
    }

    // ---- combine halves: REDG atomic add (out pre-zeroed) ----
    const int gy0 = ybase + y0;
    #pragma unroll
    for (int ry = 0; ry < 4; ++ry) {
        const int y = gy0 + ry;
        if (y < OH) {
            float* o = out + ((size_t)n * OH + y) * OW + x0;
            #pragma unroll
            for (int xc = 0; xc < 4; ++xc) {
                if (x0 + xc < OW) atomicAdd(&o[xc], acc[ry * 4 + xc]);
            }
        }
    }
}

extern "C" void kernel_launch(void* const* d_in, const int* in_sizes, int n_in,
                              void* d_out, int out_size) {
    const float* img = (const float*)d_in[0];   // [64,64,128,128] f32
    const float* ker = (const float*)d_in[1];   // [64,64,3,3]     f32
    float* out       = (float*)d_out;           // [64,1,126,126]  f32

    zero_out_kernel<<<(OUT_ELEMS / 4 + 511) / 512, 512>>>((float4*)out);
    dim3 grid(NN, N_TILES, NSPLIT);             // 1024 CTAs
    imagewise_conv2d_kernel<<<grid, NTHREADS>>>(img, ker, out);
}

// round 10
// speedup vs baseline: 1.0833x; 1.0457x over previous
#include <cuda_runtime.h>

#define NN 64
#define CC 64
#define HH 128
#define WW 128
#define HWSZ (HH * WW)
#define OH 126
#define OW 126
#define OUT_ROWS_PER_TILE 16
#define N_TILES 8
#define STAGES 3
#define NTHREADS 128
#define WROWS 6               // input rows per warp strip
#define WSTR 132              // floats per strip row (128 + pad, 16B aligned)
#define WARP_TILE (WROWS * WSTR)          // 792 floats per warp per stage
#define STAGE_TILE (4 * WARP_TILE)        // 4 warps

__device__ __forceinline__ void cp_async16(const float* smem, const float* gmem) {
    unsigned saddr = (unsigned)__cvta_generic_to_shared((void*)smem);
    asm volatile("cp.async.cg.shared.global [%0], [%1], 16;\n" :: "r"(saddr), "l"(gmem));
}
__device__ __forceinline__ void cp_commit() {
    asm volatile("cp.async.commit_group;\n" ::: "memory");
}
__device__ __forceinline__ void cp_wait1() {
    asm volatile("cp.async.wait_group 1;\n" ::: "memory");
}
__device__ __forceinline__ void cp_wait0() {
    asm volatile("cp.async.wait_group 0;\n" ::: "memory");
}

// One channel of 3x3 conv on a 4-row x 4-col output patch. Weights packed 3xfloat4.
__device__ __forceinline__ void compute_ch(const float* __restrict__ t,
                                           const float4* __restrict__ w4,
                                           float* __restrict__ acc) {
    const float4 wa = w4[0];
    const float4 wb = w4[1];
    const float w8  = ((const float*)(w4 + 2))[0];
    const float w0 = wa.x, w1 = wa.y, w2 = wa.z, w3 = wa.w;
    const float w4_ = wb.x, w5 = wb.y, w6 = wb.z, w7 = wb.w;

    #pragma unroll
    for (int j = 0; j < 6; ++j) {                 // 6 input rows -> 4 output rows
        const float* row = t + j * WSTR;
        const float4 p = *(const float4*)(row);
        const float2 q = *(const float2*)(row + 4);
        const float v0 = p.x, v1 = p.y, v2 = p.z, v3 = p.w, v4 = q.x, v5 = q.y;
        #pragma unroll
        for (int kh = 0; kh < 3; ++kh) {
            const int ro = j - kh;                // compile-time after unroll
            if (ro >= 0 && ro < 4) {
                const float a  = (kh == 0) ? w0 : (kh == 1) ? w3 : w6;
                const float b  = (kh == 0) ? w1 : (kh == 1) ? w4_ : w7;
                const float cc = (kh == 0) ? w2 : (kh == 1) ? w5 : w8;
                acc[ro * 4 + 0] = fmaf(v0, a,  acc[ro * 4 + 0]);
                acc[ro * 4 + 0] = fmaf(v1, b,  acc[ro * 4 + 0]);
                acc[ro * 4 + 0] = fmaf(v2, cc, acc[ro * 4 + 0]);
                acc[ro * 4 + 1] = fmaf(v1, a,  acc[ro * 4 + 1]);
                acc[ro * 4 + 1] = fmaf(v2, b,  acc[ro * 4 + 1]);
                acc[ro * 4 + 1] = fmaf(v3, cc, acc[ro * 4 + 1]);
                acc[ro * 4 + 2] = fmaf(v2, a,  acc[ro * 4 + 2]);
                acc[ro * 4 + 2] = fmaf(v3, b,  acc[ro * 4 + 2]);
                acc[ro * 4 + 2] = fmaf(v4, cc, acc[ro * 4 + 2]);
                acc[ro * 4 + 3] = fmaf(v3, a,  acc[ro * 4 + 3]);
                acc[ro * 4 + 3] = fmaf(v4, b,  acc[ro * 4 + 3]);
                acc[ro * 4 + 3] = fmaf(v5, cc, acc[ro * 4 + 3]);
            }
        }
    }
}

__global__ __launch_bounds__(NTHREADS, 5)
void imagewise_conv2d_kernel(const float* __restrict__ img,
                             const float* __restrict__ ker,
                             float* __restrict__ out) {
    __shared__ float4 wts4[CC * 3];                           // 12 floats / channel
    __shared__ __align__(16) float tile[STAGES][STAGE_TILE];  // warp-private strips

    const int n     = blockIdx.x;
    const int yt    = blockIdx.y;
    const int tid   = threadIdx.x;
    const int lane  = tid & 31;
    const int w     = tid >> 5;        // warp id: 4 output rows each
    const int x0    = lane * 4;        // output cols x0..x0+3
    const int ybase = yt * OUT_ROWS_PER_TILE;
    const int wy    = w * 4;           // this warp's first output row (in tile)

    // ---- stage weights, padded so each channel is 3 float4s ----
    {
        const float* kn = ker + (size_t)n * CC * 9;
        for (int e = tid; e < CC * 9; e += NTHREADS) {
            int c = e / 9;
            int i = e - c * 9;
            ((float*)&wts4[c * 3])[i] = kn[e];
        }
    }
    __syncthreads();   // the ONLY block barrier: weights visible before the loop

    // ---- hoisted per-warp copy descriptors ----
    // Warp w copies its 6 rows; lane handles one float4 per row (6 copies/thread).
    const int sbase0 = w * WARP_TILE + lane * 4;   // + i*WSTR per row
    int grow[WROWS];
    #pragma unroll
    for (int i = 0; i < WROWS; ++i) {
        int rg = ybase + wy + i;
        if (rg > HH - 1) rg = HH - 1;              // clamp halo (feeds masked rows only)
        grow[i] = rg * WW + lane * 4;
    }
    const int gr0 = grow[0], gr1 = grow[1], gr2 = grow[2],
              gr3 = grow[3], gr4 = grow[4], gr5 = grow[5];

    const float* imgn = img + (size_t)n * CC * HWSZ;

    auto issue = [&](int stage, const float* g) {
        float* sb = &tile[stage][sbase0];
        cp_async16(sb + 0 * WSTR, g + gr0);
        cp_async16(sb + 1 * WSTR, g + gr1);
        cp_async16(sb + 2 * WSTR, g + gr2);
        cp_async16(sb + 3 * WSTR, g + gr3);
        cp_async16(sb + 4 * WSTR, g + gr4);
        cp_async16(sb + 5 * WSTR, g + gr5);
        cp_commit();
    };

    // ---- prologue: channels 0 and 1 into stages 0 and 1 (per-warp groups) ----
    const float* src = imgn;
    issue(0, src); src += HWSZ;
    issue(1, src); src += HWSZ;      // src now -> channel 2

    float acc[16];
    #pragma unroll
    for (int i = 0; i < 16; ++i) acc[i] = 0.0f;

    const int rbase = w * WARP_TILE + x0;
    const float4* wp = wts4;
    int cur = 0, nxt = 2;            // nxt = (cur + 2) % 3

    for (int c = 0; c < CC; ++c) {
        // Per-warp wait: channel c's strip landed (1 newer group may fly).
        if (c + 1 < CC) cp_wait1(); else cp_wait0();
        __syncwarp();                // cross-lane visibility within the warp

        // Stage nxt was consumed by this warp at iteration c-1 -> free to refill.
        if (c + 2 < CC) { issue(nxt, src); src += HWSZ; }

        compute_ch(&tile[cur][rbase], wp, acc);
        wp += 3;
        cur = (cur == STAGES - 1) ? 0 : cur + 1;
        nxt = (nxt == STAGES - 1) ? 0 : nxt + 1;
    }

    // ---- store (mask 126-row/col edges) ----
    const int gy0 = ybase + wy;
    #pragma unroll
    for (int ry = 0; ry < 4; ++ry) {
        const int y = gy0 + ry;
        if (y < OH) {
            float* o = out + ((size_t)n * OH + y) * OW + x0;
            #pragma unroll
            for (int xc = 0; xc < 4; ++xc) {
                if (x0 + xc < OW) o[xc] = acc[ry * 4 + xc];
            }
        }
    }
}

extern "C" void kernel_launch(void* const* d_in, const int* in_sizes, int n_in,
                              void* d_out, int out_size) {
    const float* img = (const float*)d_in[0];   // [64,64,128,128] f32
    const float* ker = (const float*)d_in[1];   // [64,64,3,3]     f32
    float* out       = (float*)d_out;           // [64,1,126,126]  f32

    dim3 grid(NN, N_TILES);
    imagewise_conv2d_kernel<<<grid, NTHREADS>>>(img, ker, out);
}

// round 11
// speedup vs baseline: 1.1018x; 1.0171x over previous
#include <cuda_runtime.h>

#define NN 64
#define CC 64
#define HH 128
#define WW 128
#define HWSZ (HH * WW)
#define OH 126
#define OW 126
#define OUT_ROWS_PER_TILE 16
#define N_TILES 8
#define NHALF 2               // column halves -> grid 1024 for SM balance
#define TILE_ROWS 18          // 16 output rows + 2 halo
#define SROW 72               // 68 loaded floats + pad (16B aligned)
#define SM_TILE (TILE_ROWS * SROW)
#define STAGES 3
#define NTHREADS 64
#define F4_PER_ROW 17         // 68 floats per row
#define CP_PER_STAGE (TILE_ROWS * F4_PER_ROW)   // 306 float4 copies

__device__ __forceinline__ void cp_async16(const float* smem, const float* gmem) {
    unsigned saddr = (unsigned)__cvta_generic_to_shared((void*)smem);
    asm volatile("cp.async.cg.shared.global [%0], [%1], 16;\n" :: "r"(saddr), "l"(gmem));
}
__device__ __forceinline__ void cp_commit() {
    asm volatile("cp.async.commit_group;\n" ::: "memory");
}
__device__ __forceinline__ void cp_wait1() {
    asm volatile("cp.async.wait_group 1;\n" ::: "memory");
}
__device__ __forceinline__ void cp_wait0() {
    asm volatile("cp.async.wait_group 0;\n" ::: "memory");
}

// One channel of 3x3 conv on a 4-row x 4-col output patch. Weights packed 3xfloat4.
__device__ __forceinline__ void compute_ch(const float* __restrict__ t,
                                           const float4* __restrict__ w4,
                                           float* __restrict__ acc) {
    const float4 wa = w4[0];
    const float4 wb = w4[1];
    const float w8  = ((const float*)(w4 + 2))[0];
    const float w0 = wa.x, w1 = wa.y, w2 = wa.z, w3 = wa.w;
    const float w4_ = wb.x, w5 = wb.y, w6 = wb.z, w7 = wb.w;

    #pragma unroll
    for (int j = 0; j < 6; ++j) {                 // 6 input rows -> 4 output rows
        const float* row = t + j * SROW;
        const float4 p = *(const float4*)(row);
        const float2 q = *(const float2*)(row + 4);
        const float v0 = p.x, v1 = p.y, v2 = p.z, v3 = p.w, v4 = q.x, v5 = q.y;
        #pragma unroll
        for (int kh = 0; kh < 3; ++kh) {
            const int ro = j - kh;                // compile-time after unroll
            if (ro >= 0 && ro < 4) {
                const float a  = (kh == 0) ? w0 : (kh == 1) ? w3 : w6;
                const float b  = (kh == 0) ? w1 : (kh == 1) ? w4_ : w7;
                const float cc = (kh == 0) ? w2 : (kh == 1) ? w5 : w8;
                acc[ro * 4 + 0] = fmaf(v0, a,  acc[ro * 4 + 0]);
                acc[ro * 4 + 0] = fmaf(v1, b,  acc[ro * 4 + 0]);
                acc[ro * 4 + 0] = fmaf(v2, cc, acc[ro * 4 + 0]);
                acc[ro * 4 + 1] = fmaf(v1, a,  acc[ro * 4 + 1]);
                acc[ro * 4 + 1] = fmaf(v2, b,  acc[ro * 4 + 1]);
                acc[ro * 4 + 1] = fmaf(v3, cc, acc[ro * 4 + 1]);
                acc[ro * 4 + 2] = fmaf(v2, a,  acc[ro * 4 + 2]);
                acc[ro * 4 + 2] = fmaf(v3, b,  acc[ro * 4 + 2]);
                acc[ro * 4 + 2] = fmaf(v4, cc, acc[ro * 4 + 2]);
                acc[ro * 4 + 3] = fmaf(v3, a,  acc[ro * 4 + 3]);
                acc[ro * 4 + 3] = fmaf(v4, b,  acc[ro * 4 + 3]);
                acc[ro * 4 + 3] = fmaf(v5, cc, acc[ro * 4 + 3]);
            }
        }
    }
}

__global__ __launch_bounds__(NTHREADS, 8)
void imagewise_conv2d_kernel(const float* __restrict__ img,
                             const float* __restrict__ ker,
                             float* __restrict__ out) {
    __shared__ float4 wts4[CC * 3];                        // 12 floats / channel (padded)
    __shared__ __align__(16) float tile[STAGES][SM_TILE];  // 3-stage ring

    const int n     = blockIdx.x;
    const int yt    = blockIdx.y;
    const int h     = blockIdx.z;      // column half
    const int tid   = threadIdx.x;
    const int tx    = tid & 15;        // 16 col-groups x 4 cols
    const int ty    = tid >> 4;        // 4 row-groups  x 4 rows
    const int y0    = ty * 4;
    const int ybase = yt * OUT_ROWS_PER_TILE;
    const int gcol0 = h ? 60 : 0;      // gmem float-col base of the 68-col load window
    const int x0s   = tx * 4 + (h ? 4 : 0);   // smem col of this thread's patch
    const int gx0   = h * 64 + tx * 4;        // global output col

    // ---- stage weights, padded so each channel is 3 float4s ----
    {
        const float* kn = ker + (size_t)n * CC * 9;
        for (int e = tid; e < CC * 9; e += NTHREADS) {
            int c = e / 9;
            int i = e - c * 9;
            ((float*)&wts4[c * 3])[i] = kn[e];
        }
    }

    // ---- hoisted copy descriptors (loop-invariant across channels) ----
    // 306 float4 copies / 64 threads = 4 full rounds + 1 partial (tid < 50).
    int soff[5], goff[5];
    #pragma unroll
    for (int k = 0; k < 5; ++k) {
        int idx = tid + k * NTHREADS;
        if (idx < CP_PER_STAGE) {
            int r  = idx / F4_PER_ROW;
            int c4 = (idx - r * F4_PER_ROW) * 4;
            int rg = ybase + r; if (rg > HH - 1) rg = HH - 1;   // clamp halo
            soff[k] = r * SROW + c4;
            goff[k] = rg * WW + gcol0 + c4;
        } else {
            soff[k] = 0; goff[k] = 0;
        }
    }
    const int  s0 = soff[0], s1 = soff[1], s2 = soff[2], s3 = soff[3], s4 = soff[4];
    const int  g0 = goff[0], g1 = goff[1], g2 = goff[2], g3 = goff[3], g4 = goff[4];
    const bool has5 = (tid + 4 * NTHREADS) < CP_PER_STAGE;   // tid < 50

    const float* imgn = img + (size_t)n * CC * HWSZ;

    auto issue = [&](float* sbase, const float* g) {
        cp_async16(sbase + s0, g + g0);
        cp_async16(sbase + s1, g + g1);
        cp_async16(sbase + s2, g + g2);
        cp_async16(sbase + s3, g + g3);
        if (has5) cp_async16(sbase + s4, g + g4);
        cp_commit();
    };

    // ---- prologue: channels 0 and 1 into stages 0 and 1 ----
    const float* src = imgn;
    issue(&tile[0][0], src); src += HWSZ;
    issue(&tile[1][0], src); src += HWSZ;      // src now -> channel 2

    float acc[16];
    #pragma unroll
    for (int i = 0; i < 16; ++i) acc[i] = 0.0f;

    const int yx = y0 * SROW + x0s;
    const float4* wp = wts4;
    int cur = 0, nxt = 2;                      // nxt = (cur + 2) % 3

    for (int c = 0; c < CC; ++c) {
        if (c + 1 < CC) cp_wait1(); else cp_wait0();
        __syncthreads();   // c's data visible (and, first iter, weights); c-1 compute done

        if (c + 2 < CC) { issue(&tile[nxt][0], src); src += HWSZ; }

        compute_ch(&tile[cur][yx], wp, acc);
        wp += 3;
        cur = (cur == STAGES - 1) ? 0 : cur + 1;
        nxt = (nxt == STAGES - 1) ? 0 : nxt + 1;
    }

    // ---- store (mask 126-row/col edges) ----
    const int gy0 = ybase + y0;
    #pragma unroll
    for (int ry = 0; ry < 4; ++ry) {
        const int y = gy0 + ry;
        if (y < OH) {
            float* o = out + ((size_t)n * OH + y) * OW + gx0;
            #pragma unroll
            for (int xc = 0; xc < 4; ++xc) {
                if (gx0 + xc < OW) o[xc] = acc[ry * 4 + xc];
            }
        }
    }
}

extern "C" void kernel_launch(void* const* d_in, const int* in_sizes, int n_in,
                              void* d_out, int out_size) {
    const float* img = (const float*)d_in[0];   // [64,64,128,128] f32
    const float* ker = (const float*)d_in[1];   // [64,64,3,3]     f32
    float* out       = (float*)d_out;           // [64,1,126,126]  f32

    dim3 grid(NN, N_TILES, NHALF);              // 1024 CTAs -> ~6.92/SM, 1.2% imbalance
    imagewise_conv2d_kernel<<<grid, NTHREADS>>>(img, ker, out);
}

// round 12
// speedup vs baseline: 1.1143x; 1.0113x over previous
#include <cuda_runtime.h>

#define NN 64
#define CC 64
#define HH 128
#define WW 128
#define HWSZ (HH * WW)
#define OH 126
#define OW 126
#define ORPT 16               // output rows per CTA tile
#define N_TILES 8
#define NTHREADS 128          // 4 warps x (32 lanes x 4 cols = full 128-col row)

__global__ __launch_bounds__(NTHREADS, 4)
void imagewise_conv2d_kernel(const float* __restrict__ img,
                             const float* __restrict__ ker,
                             float* __restrict__ out) {
    __shared__ float4 wts4[CC * 3];    // 12 floats / channel (padded for float4 LDS)

    const int n     = blockIdx.x;
    const int yt    = blockIdx.y;
    const int tid   = threadIdx.x;
    const int lane  = tid & 31;
    const int w     = tid >> 5;        // warp -> 4 output rows
    const int gx    = lane * 4;        // output cols gx..gx+3
    const int ybase = yt * ORPT;
    const int wy    = w * 4;

    // ---- stage weights (only use of smem; only barrier in the kernel) ----
    {
        const float* kn = ker + (size_t)n * CC * 9;
        for (int e = tid; e < CC * 9; e += NTHREADS) {
            int c = e / 9, i = e - c * 9;
            ((float*)&wts4[c * 3])[i] = kn[e];
        }
    }
    __syncthreads();

    // ---- per-thread row pointers (6 input rows, clamped; clamped rows feed masked outputs) ----
    const float* imgn = img + (size_t)n * CC * HWSZ;
    const float* rp[6];
    #pragma unroll
    for (int j = 0; j < 6; ++j) {
        int rg = ybase + wy + j; if (rg > HH - 1) rg = HH - 1;
        rp[j] = imgn + rg * WW + gx;
    }
    // halo re-read offset; lane 31 would go OOB -> read own data (feeds masked cols only)
    const int qoff = (lane == 31) ? 0 : 4;

    float4 P0[6], P1[6];
    #pragma unroll
    for (int j = 0; j < 6; ++j) P0[j] = *(const float4*)(rp[j]);   // channel 0

    float acc[16];
    #pragma unroll
    for (int i = 0; i < 16; ++i) acc[i] = 0.0f;

    const float4* wp = wts4;

    #define LOADP(Pb, OFS)                                                      \
        do {                                                                    \
            _Pragma("unroll")                                                   \
            for (int j = 0; j < 6; ++j)                                         \
                Pb[j] = *(const float4*)(rp[j] + (OFS));                        \
        } while (0)

    // Compute one channel from register rows Pb; v4/v5 re-read through L1.
    #define COMPUTE(Pb, QO)                                                     \
        do {                                                                    \
            const float4 wa = wp[0];                                            \
            const float4 wb = wp[1];                                            \
            const float  w8 = ((const float*)(wp + 2))[0];                      \
            const float w0=wa.x,w1=wa.y,w2=wa.z,w3=wa.w;                        \
            const float w4_=wb.x,w5=wb.y,w6=wb.z,w7=wb.w;                       \
            _Pragma("unroll")                                                   \
            for (int j = 0; j < 6; ++j) {                                       \
                const float4 p = Pb[j];                                         \
                const float2 q = *(const float2*)(rp[j] + (QO) + qoff);         \
                const float v0=p.x,v1=p.y,v2=p.z,v3=p.w,v4=q.x,v5=q.y;          \
                _Pragma("unroll")                                               \
                for (int kh = 0; kh < 3; ++kh) {                                \
                    const int ro = j - kh;                                      \
                    if (ro >= 0 && ro < 4) {                                    \
                        const float a =(kh==0)?w0:(kh==1)?w3:w6;                \
                        const float b =(kh==0)?w1:(kh==1)?w4_:w7;               \
                        const float cc=(kh==0)?w2:(kh==1)?w5:w8;                \
                        acc[ro*4+0]=fmaf(v0,a, acc[ro*4+0]);                    \
                        acc[ro*4+0]=fmaf(v1,b, acc[ro*4+0]);                    \
                        acc[ro*4+0]=fmaf(v2,cc,acc[ro*4+0]);                    \
                        acc[ro*4+1]=fmaf(v1,a, acc[ro*4+1]);                    \
                        acc[ro*4+1]=fmaf(v2,b, acc[ro*4+1]);                    \
                        acc[ro*4+1]=fmaf(v3,cc,acc[ro*4+1]);                    \
                        acc[ro*4+2]=fmaf(v2,a, acc[ro*4+2]);                    \
                        acc[ro*4+2]=fmaf(v3,b, acc[ro*4+2]);                    \
                        acc[ro*4+2]=fmaf(v4,cc,acc[ro*4+2]);                    \
                        acc[ro*4+3]=fmaf(v3,a, acc[ro*4+3]);                    \
                        acc[ro*4+3]=fmaf(v4,b, acc[ro*4+3]);                    \
                        acc[ro*4+3]=fmaf(v5,cc,acc[ro*4+3]);                    \
                    }                                                           \
                }                                                               \
            }                                                                   \
            wp += 3;                                                            \
        } while (0)

    // Channel loop, unrolled x2 for compile-time register buffers. No barriers.
    for (int c = 0; c < CC; c += 2) {
        LOADP(P1, HWSZ);                       // prefetch channel c+1
        COMPUTE(P0, 0);                        // compute channel c
        if (c + 2 < CC) LOADP(P0, 2 * HWSZ);   // prefetch channel c+2
        COMPUTE(P1, HWSZ);                     // compute channel c+1
        #pragma unroll
        for (int j = 0; j < 6; ++j) rp[j] += 2 * HWSZ;
    }
    #undef LOADP
    #undef COMPUTE

    // ---- store (mask 126-row/col edges) ----
    const int gy0 = ybase + wy;
    #pragma unroll
    for (int ry = 0; ry < 4; ++ry) {
        const int y = gy0 + ry;
        if (y < OH) {
            float* o = out + ((size_t)n * OH + y) * OW + gx;
            #pragma unroll
            for (int xc = 0; xc < 4; ++xc) {
                if (gx + xc < OW) o[xc] = acc[ry * 4 + xc];
            }
        }
    }
}

extern "C" void kernel_launch(void* const* d_in, const int* in_sizes, int n_in,
                              void* d_out, int out_size) {
    const float* img = (const float*)d_in[0];   // [64,64,128,128] f32
    const float* ker = (const float*)d_in[1];   // [64,64,3,3]     f32
    float* out       = (float*)d_out;           // [64,1,126,126]  f32

    dim3 grid(NN, N_TILES);
    imagewise_conv2d_kernel<<<grid, NTHREADS>>>(img, ker, out);
}